// round 2
// baseline (speedup 1.0000x reference)
#include <cuda_runtime.h>
#include <cuda_bf16.h>

// x viewed as [T=16384 tokens][H=32 heads][D=128 dims], fp32.
// For each (t, d): 32-point Walsh-Hadamard across h, * 1/sqrt(32).
// Column index col = t*128 + d. Consecutive lanes -> consecutive d
// -> every strided access is warp-coalesced (128B per warp per h).

#define NUM_HEADS 32
#define HEAD_DIM  128
#define HIDDEN    (NUM_HEADS * HEAD_DIM)   // 4096

__global__ __launch_bounds__(256) void had32_kernel(
    const float* __restrict__ x, float* __restrict__ out, long n_cols)
{
    long col = (long)blockIdx.x * blockDim.x + threadIdx.x;
    if (col >= n_cols) return;

    long t = col >> 7;          // col / 128
    int  d = (int)(col & 127);  // col % 128

    const float* __restrict__ in_base  = x   + (t << 12) + d;  // t*4096 + d
    float*       __restrict__ out_base = out + (t << 12) + d;

    float v[NUM_HEADS];
    #pragma unroll
    for (int h = 0; h < NUM_HEADS; ++h)
        v[h] = in_base[h << 7];   // stride 128 floats, coalesced across lanes

    // In-place fast WHT, Sylvester ordering (matches reference butterfly).
    #pragma unroll
    for (int len = 1; len < NUM_HEADS; len <<= 1) {
        #pragma unroll
        for (int i = 0; i < NUM_HEADS; ++i) {
            if ((i & len) == 0) {
                float a = v[i];
                float b = v[i + len];
                v[i]       = a + b;
                v[i + len] = a - b;
            }
        }
    }

    const float scale = 0.17677669529663687f;  // 1/sqrt(32)
    #pragma unroll
    for (int h = 0; h < NUM_HEADS; ++h)
        out_base[h << 7] = v[h] * scale;
}

extern "C" void kernel_launch(void* const* d_in, const int* in_sizes, int n_in,
                              void* d_out, int out_size)
{
    const float* x = (const float*)d_in[0];
    float* out = (float*)d_out;

    long n = (long)in_sizes[0];          // total elements (e.g. 4*4096*4096)
    long n_cols = n / NUM_HEADS;         // one thread per (token, dim) column

    int threads = 256;
    long blocks = (n_cols + threads - 1) / threads;
    had32_kernel<<<(unsigned)blocks, threads>>>(x, out, n_cols);
}